// round 13
// baseline (speedup 1.0000x reference)
#include <cuda_runtime.h>
#include <math.h>

#define N 4096
#define D 128
#define NB 32
#define ALPHA 10.0f
#define BETA 2.0f
#define BASE 0.5f
#define BIGF 1e30f
#define LOG2E 1.4426950408889634f

// ---------------- device scratch (static zero-init; no allocation allowed) ----------------
__device__ float         g_sim[(size_t)N * N];   // 64 MB similarity matrix
// Pre-converted TF32 operand arrays in MMA-fragment layout (2 MB each, L2-resident):
//  A (m16 tiles):  idx = ((tile16*16 + s)*32 + lane)*4 + r ; lane=(m&7)*4+(k8&3), r=((m>>3)&1)+2*(k8>>2)
//  B (n8 tiles):   idx = ((tile8 *16 + s)*32 + lane)*2 + r ; lane=(n&7)*4+(k8&3), r=k8>>2
__device__ float         g_Ahi[(size_t)N * D];
__device__ float         g_Alo[(size_t)N * D];
__device__ float         g_Bhi[(size_t)N * D];
__device__ float         g_Blo[(size_t)N * D];
// Encoded extrema with ZERO identity (valid static init, idempotent across graph replays):
//  g_eminpos[r] = max over positives of f2u(-sim)  -> minpos = -u2f(val); 0 => empty => +BIGF
//  g_emaxneg[r] = max over negatives of f2u(+sim)  -> maxneg =  u2f(val); 0 => empty => -BIGF
__device__ unsigned      g_eminpos[N];
__device__ unsigned      g_emaxneg[N];
__device__ unsigned char g_t8[N];                // targets as uint8 (written by diagonal blocks)

// order-preserving float<->uint transforms (unsigned compare == float compare)
__device__ __forceinline__ unsigned f2u(float f) {
    unsigned b = __float_as_uint(f);
    return (b & 0x80000000u) ? ~b : (b | 0x80000000u);
}
__device__ __forceinline__ float u2f(unsigned u) {
    return (u & 0x80000000u) ? __uint_as_float(u ^ 0x80000000u) : __uint_as_float(~u);
}

__device__ __forceinline__ unsigned tf32_rna(float x) {
    unsigned r;
    asm("cvt.rna.tf32.f32 %0, %1;" : "=r"(r) : "f"(x));
    return r;
}
__device__ __forceinline__ float ex2(float x) {
    float r;
    asm("ex2.approx.f32 %0, %1;" : "=f"(r) : "f"(x));
    return r;
}

// m16n8k8 tf32 mma: D += A*B (row.col), fp32 accumulate
__device__ __forceinline__ void mma_tf32(float* c, const uint4& a, const uint2& b) {
    asm volatile(
        "mma.sync.aligned.m16n8k8.row.col.f32.tf32.tf32.f32 "
        "{%0,%1,%2,%3}, {%4,%5,%6,%7}, {%8,%9}, {%0,%1,%2,%3};"
        : "+f"(c[0]), "+f"(c[1]), "+f"(c[2]), "+f"(c[3])
        : "r"(a.x), "r"(a.y), "r"(a.z), "r"(a.w), "r"(b.x), "r"(b.y));
}

// ---------------- kernel: one-time tf32 hi/lo conversion into fragment layouts ----------------
__global__ void k_cvt(const float* __restrict__ X) {
    const int b = blockIdx.x;
    if (b < 512) {
        int f = b * 256 + threadIdx.x;            // float4 index, 0..131071
        int tile16 = f >> 9, rem = f & 511, s = rem >> 5, lane = rem & 31;
        int g9 = lane >> 2, q = lane & 3;
        float hi[4], lo[4];
        #pragma unroll
        for (int r = 0; r < 4; r++) {
            int m = tile16 * 16 + g9 + 8 * (r & 1);
            int k = s * 8 + q + 4 * (r >> 1);
            float v = X[m * D + k];
            unsigned h = tf32_rna(v);
            hi[r] = __uint_as_float(h);
            lo[r] = __uint_as_float(tf32_rna(v - __uint_as_float(h)));
        }
        *reinterpret_cast<float4*>(&g_Ahi[(size_t)f * 4]) = make_float4(hi[0], hi[1], hi[2], hi[3]);
        *reinterpret_cast<float4*>(&g_Alo[(size_t)f * 4]) = make_float4(lo[0], lo[1], lo[2], lo[3]);
    } else {
        int f = (b - 512) * 256 + threadIdx.x;    // float2 index, 0..262143
        int tile8 = f >> 9, rem = f & 511, s = rem >> 5, lane = rem & 31;
        int n = tile8 * 8 + (lane >> 2), q = lane & 3;
        float hi[2], lo[2];
        #pragma unroll
        for (int r = 0; r < 2; r++) {
            int k = s * 8 + q + 4 * r;
            float v = X[n * D + k];
            unsigned h = tf32_rna(v);
            hi[r] = __uint_as_float(h);
            lo[r] = __uint_as_float(tf32_rna(v - __uint_as_float(h)));
        }
        *reinterpret_cast<float2*>(&g_Bhi[(size_t)f * 2]) = make_float2(hi[0], hi[1]);
        *reinterpret_cast<float2*>(&g_Blo[(size_t)f * 2]) = make_float2(lo[0], lo[1]);
    }
}

// ---------------- kernel: sim = X X^T (3xTF32), upper triangle, fused extrema ----------------
// Triangle-packed 528 blocks, 256 threads = 8 warps (2x4), warp tile 64x32.
// Mainloop: fragments LDG'd directly from pre-converted layout arrays; no smem, no barriers.
// MMA issue is PASS-MAJOR (16x hh, 16x hl, 16x lh) so consecutive MMAs never share an
// accumulator (RAW distance 3 -> 16); per-accumulator fp order unchanged (bitwise identical).
__global__ __launch_bounds__(256, 2) void k_gemm(const int* __restrict__ tgt,
                                                 float* __restrict__ out, int out_size) {
    __shared__ __align__(16) float sm[9216];   // epilogue staging only (8 x 1152)
    __shared__ int sIs64;

    const int tid = threadIdx.x;

    if (tid < 32) {
        int bad = 0;
        #pragma unroll
        for (int i = 0; i < 4; i++)
            if (tgt[1 + 2 * (tid + 32 * i)] != 0) bad = 1;
        unsigned anyBad = __ballot_sync(0xFFFFFFFFu, bad);
        if (tid == 0) sIs64 = (anyBad == 0);
    }
    if (blockIdx.x == 0 && tid == 0 && out_size >= 1) out[0] = 0.0f;
    __syncthreads();
    const int is64 = sIs64;

    const int lin = blockIdx.x;
    int bi = (int)(32.5f - sqrtf(32.5f * 32.5f - 2.0f * (float)lin));
    #define TRI_OFF(r) ((r) * NB - ((r) * ((r) - 1)) / 2)
    while (bi > 0 && TRI_OFF(bi) > lin) bi--;
    while (bi < NB - 1 && TRI_OFF(bi + 1) <= lin) bi++;
    const int bj = bi + (lin - TRI_OFF(bi));
    #undef TRI_OFF

    const int rowBase = bi * 128;
    const int colBase = bj * 128;

    const int w    = tid >> 5;
    const int lane = tid & 31;
    const int wr   = w >> 2;
    const int wc   = w & 3;
    const int g    = lane >> 2;
    const int q    = lane & 3;

    float c[4][4][4];
    #pragma unroll
    for (int mt = 0; mt < 4; mt++)
        #pragma unroll
        for (int nt = 0; nt < 4; nt++)
            #pragma unroll
            for (int r = 0; r < 4; r++) c[mt][nt][r] = 0.0f;

    const int aBase = ((bi * 8 + wr * 4) * 16) * 32 + lane;
    const int bBase = ((bj * 16 + wc * 4) * 16) * 32 + lane;

    #pragma unroll 2
    for (int s = 0; s < 16; s++) {
        uint4 ah[4], al[4];
        uint2 bh[4], bl[4];
        #pragma unroll
        for (int mt = 0; mt < 4; mt++) {
            size_t idx = (size_t)(aBase + mt * 512 + s * 32) * 4;
            ah[mt] = *reinterpret_cast<const uint4*>(&g_Ahi[idx]);
            al[mt] = *reinterpret_cast<const uint4*>(&g_Alo[idx]);
        }
        #pragma unroll
        for (int nt = 0; nt < 4; nt++) {
            size_t idx = (size_t)(bBase + nt * 512 + s * 32) * 2;
            bh[nt] = *reinterpret_cast<const uint2*>(&g_Bhi[idx]);
            bl[nt] = *reinterpret_cast<const uint2*>(&g_Blo[idx]);
        }
        // pass-major issue: no back-to-back same-accumulator MMAs
        #pragma unroll
        for (int mt = 0; mt < 4; mt++)
            #pragma unroll
            for (int nt = 0; nt < 4; nt++)
                mma_tf32(c[mt][nt], ah[mt], bh[nt]);
        #pragma unroll
        for (int mt = 0; mt < 4; mt++)
            #pragma unroll
            for (int nt = 0; nt < 4; nt++)
                mma_tf32(c[mt][nt], ah[mt], bl[nt]);
        #pragma unroll
        for (int mt = 0; mt < 4; mt++)
            #pragma unroll
            for (int nt = 0; nt < 4; nt++)
                mma_tf32(c[mt][nt], al[mt], bh[nt]);
    }

    // ---------------- epilogue (verified) ----------------
    #define TGT(i) (is64 ? (int)((const long long*)tgt)[i] : tgt[i])
    int trow[8], tcol[8];
    #pragma unroll
    for (int mt = 0; mt < 4; mt++)
        #pragma unroll
        for (int h = 0; h < 2; h++)
            trow[mt * 2 + h] = TGT(rowBase + wr * 64 + mt * 16 + g + 8 * h);
    #pragma unroll
    for (int nt = 0; nt < 4; nt++)
        #pragma unroll
        for (int p = 0; p < 2; p++)
            tcol[nt * 2 + p] = TGT(colBase + wc * 32 + nt * 8 + q * 2 + p);

    if (bi == bj && tid < 128)
        g_t8[rowBase + tid] = (unsigned char)TGT(rowBase + tid);
    #undef TGT

    float rMin[8], rMax[8], cMin[8], cMax[8];
    #pragma unroll
    for (int k = 0; k < 8; k++) { rMin[k] = BIGF; rMax[k] = -BIGF; cMin[k] = BIGF; cMax[k] = -BIGF; }
    #pragma unroll
    for (int mt = 0; mt < 4; mt++)
        #pragma unroll
        for (int nt = 0; nt < 4; nt++)
            #pragma unroll
            for (int r = 0; r < 4; r++) {
                int h = r >> 1, p = r & 1;
                float s = c[mt][nt][r];
                if (trow[mt * 2 + h] == tcol[nt * 2 + p]) {
                    if (s < 1.0f) {
                        rMin[mt * 2 + h] = fminf(rMin[mt * 2 + h], s);
                        cMin[nt * 2 + p] = fminf(cMin[nt * 2 + p], s);
                    }
                } else {
                    rMax[mt * 2 + h] = fmaxf(rMax[mt * 2 + h], s);
                    cMax[nt * 2 + p] = fmaxf(cMax[nt * 2 + p], s);
                }
            }

    #pragma unroll
    for (int o = 1; o <= 2; o <<= 1)
        #pragma unroll
        for (int k = 0; k < 8; k++) {
            rMin[k] = fminf(rMin[k], __shfl_xor_sync(0xFFFFFFFFu, rMin[k], o));
            rMax[k] = fmaxf(rMax[k], __shfl_xor_sync(0xFFFFFFFFu, rMax[k], o));
        }
    if (q == 0) {
        #pragma unroll
        for (int k = 0; k < 8; k++) {
            int row = rowBase + wr * 64 + (k >> 1) * 16 + g + 8 * (k & 1);
            atomicMax(&g_eminpos[row], f2u(-rMin[k]));
            atomicMax(&g_emaxneg[row], f2u(rMax[k]));
        }
    }
    #pragma unroll
    for (int o = 4; o <= 16; o <<= 1)
        #pragma unroll
        for (int k = 0; k < 8; k++) {
            cMin[k] = fminf(cMin[k], __shfl_xor_sync(0xFFFFFFFFu, cMin[k], o));
            cMax[k] = fmaxf(cMax[k], __shfl_xor_sync(0xFFFFFFFFu, cMax[k], o));
        }
    if (g == 0) {
        #pragma unroll
        for (int k = 0; k < 8; k++) {
            int col = colBase + wc * 32 + (k >> 1) * 8 + q * 2 + (k & 1);
            atomicMax(&g_eminpos[col], f2u(-cMin[k]));
            atomicMax(&g_emaxneg[col], f2u(cMax[k]));
        }
    }

    float* S = sm + w * 1152;
    #pragma unroll
    for (int h2 = 0; h2 < 2; h2++) {
        #pragma unroll
        for (int mt2 = 0; mt2 < 2; mt2++) {
            int mt = h2 * 2 + mt2;
            #pragma unroll
            for (int nt = 0; nt < 4; nt++)
                #pragma unroll
                for (int r = 0; r < 4; r++)
                    S[(mt2 * 16 + g + 8 * (r >> 1)) * 36 + nt * 8 + q * 2 + (r & 1)] = c[mt][nt][r];
        }
        __syncwarp();
        #pragma unroll
        for (int pass = 0; pass < 8; pass++) {
            int idx = pass * 32 + lane;
            int lr = idx >> 3, qq = idx & 7;
            float4 v = *reinterpret_cast<const float4*>(&S[lr * 36 + qq * 4]);
            *reinterpret_cast<float4*>(
                &g_sim[(size_t)(rowBase + wr * 64 + h2 * 32 + lr) * N + colBase + wc * 32 + qq * 4]) = v;
        }
        __syncwarp();
        #pragma unroll
        for (int mt2 = 0; mt2 < 2; mt2++) {
            int mt = h2 * 2 + mt2;
            #pragma unroll
            for (int nt = 0; nt < 4; nt++)
                #pragma unroll
                for (int r = 0; r < 4; r++)
                    S[(nt * 8 + q * 2 + (r & 1)) * 36 + mt2 * 16 + g + 8 * (r >> 1)] = c[mt][nt][r];
        }
        __syncwarp();
        #pragma unroll
        for (int pass = 0; pass < 8; pass++) {
            int idx = pass * 32 + lane;
            int lr = idx >> 3, qq = idx & 7;
            float4 v = *reinterpret_cast<const float4*>(&S[lr * 36 + qq * 4]);
            *reinterpret_cast<float4*>(
                &g_sim[(size_t)(colBase + wc * 32 + lr) * N + rowBase + wr * 64 + h2 * 32 + qq * 4]) = v;
        }
        __syncwarp();
    }
}

// ---------------- kernel: mining (branchless) + masked exp sums + loss ----------------
// Warp-per-row: 512 blocks x 256 threads; warp-only reduction; single wave.
__global__ __launch_bounds__(256) void k_mine(const float* __restrict__ margin,
                                              const float* __restrict__ weight,
                                              float* __restrict__ out, int out_size) {
    const int lane = threadIdx.x & 31;
    const int warp = threadIdx.x >> 5;
    const int row  = blockIdx.x * 8 + warp;

    const float4* srow4 = reinterpret_cast<const float4*>(&g_sim[(size_t)row * N]);
    const uchar4* t4    = reinterpret_cast<const uchar4*>(g_t8);

    const int   tr = g_t8[row];
    const float m  = margin[row];
    const float wt = weight[row];
    unsigned um = g_eminpos[row];
    unsigned ux = g_emaxneg[row];
    const float minp = um ? -u2f(um) : BIGF;
    const float maxn = ux ? u2f(ux) : -BIGF;

    const float kn = ALPHA * wt * LOG2E, cn = -ALPHA * BASE * LOG2E;
    const float kp = -BETA * wt * LOG2E, cp = BETA * BASE * LOG2E;

    float ps = 0.f, ns = 0.f;
    int ap = 0, an = 0;

    #define PROC(S, TJ)                                                     \
        do {                                                                \
            float s_ = (S);                                                 \
            bool isP = ((int)(TJ) == tr);                                   \
            float en = ex2(fmaf(s_, kn, cn));                               \
            float ep = ex2(fmaf(s_, kp, cp));                               \
            bool pc = isP && (s_ < 1.0f) && ((maxn - s_) + m > 0.0f);       \
            bool nc = (!isP) && (((s_ + m) - minp) > 0.0f);                 \
            ps += pc ? ep : 0.0f;                                           \
            ns += nc ? en : 0.0f;                                           \
            ap += pc;                                                       \
            an += nc;                                                       \
        } while (0)

    #pragma unroll
    for (int cch = 0; cch < 4; cch++) {
        float4 s[8];
        uchar4 t[8];
        #pragma unroll
        for (int i = 0; i < 8; i++) {
            int idx = cch * 256 + i * 32 + lane;
            s[i] = srow4[idx];
            t[i] = t4[idx];
        }
        #pragma unroll
        for (int i = 0; i < 8; i++) {
            PROC(s[i].x, t[i].x);
            PROC(s[i].y, t[i].y);
            PROC(s[i].z, t[i].z);
            PROC(s[i].w, t[i].w);
        }
    }
    #undef PROC

    #pragma unroll
    for (int o = 16; o >= 1; o >>= 1) {
        ps += __shfl_xor_sync(0xFFFFFFFFu, ps, o);
        ns += __shfl_xor_sync(0xFFFFFFFFu, ns, o);
        ap += __shfl_xor_sync(0xFFFFFFFFu, ap, o);
        an += __shfl_xor_sync(0xFFFFFFFFu, an, o);
    }

    if (lane == 0) {
        int valid = (ap + an) >= 1;
        float li = valid ? ((2.0f / BETA) * log1pf(ps) + (2.0f / ALPHA) * log1pf(ns)) : 0.0f;
        if (out_size >= 1) atomicAdd(out, li * (1.0f / (float)N));
        if (out_size >= 1 + 2 * N) {
            out[1 + row]     = valid ? (float)ap : 0.0f;
            out[1 + N + row] = valid ? (float)an : 0.0f;
        }
    }
}

// ---------------- launch ----------------
extern "C" void kernel_launch(void* const* d_in, const int* in_sizes, int n_in,
                              void* d_out, int out_size) {
    const float* X      = (const float*)d_in[0];
    const int*   tgt    = (const int*)d_in[1];
    const float* margin = (const float*)d_in[2];
    const float* weight = (const float*)d_in[3];
    float* out = (float*)d_out;

    k_cvt<<<1536, 256>>>(X);
    k_gemm<<<528, 256>>>(tgt, out, out_size);
    k_mine<<<512, 256>>>(margin, weight, out, out_size);
}

// round 14
// speedup vs baseline: 1.3425x; 1.3425x over previous
#include <cuda_runtime.h>
#include <cuda_fp16.h>
#include <math.h>

#define N 4096
#define D 128
#define NB 32
#define ALPHA 10.0f
#define BETA 2.0f
#define BASE 0.5f
#define BIGF 1e30f
#define LOG2E 1.4426950408889634f

// ---------------- device scratch (static zero-init; no allocation allowed) ----------------
__device__ float         g_sim[(size_t)N * N];   // 64 MB similarity matrix
// Pre-converted FP16 hi/lo operand arrays in m16n8k16 fragment layout (1 MB each, L2-resident).
//  A (m16 tiles, 8 k16-steps): slot = (t*8+s)*32+lane ; 4 half2 regs per slot:
//    r0=(m=16t+g, k=16s+2q,+1) r1=(m+8, k) r2=(m, k+8,+9) r3=(m+8, k+8,+9)
//  B (n8 tiles):               slot = (nt*8+s)*32+lane ; 2 half2 regs per slot:
//    r0=(k=16s+2q,+1, n=8nt+g) r1=(k+8,+9, n)
__device__ unsigned      g_Ah[(size_t)65536 * 4];
__device__ unsigned      g_Al[(size_t)65536 * 4];
__device__ unsigned      g_Bh[(size_t)131072 * 2];
__device__ unsigned      g_Bl[(size_t)131072 * 2];
// Encoded extrema with ZERO identity (valid static init, idempotent across graph replays):
//  g_eminpos[r] = max over positives of f2u(-sim)  -> minpos = -u2f(val); 0 => empty => +BIGF
//  g_emaxneg[r] = max over negatives of f2u(+sim)  -> maxneg =  u2f(val); 0 => empty => -BIGF
__device__ unsigned      g_eminpos[N];
__device__ unsigned      g_emaxneg[N];
__device__ unsigned char g_t8[N];                // targets as uint8

// order-preserving float<->uint transforms (unsigned compare == float compare)
__device__ __forceinline__ unsigned f2u(float f) {
    unsigned b = __float_as_uint(f);
    return (b & 0x80000000u) ? ~b : (b | 0x80000000u);
}
__device__ __forceinline__ float u2f(unsigned u) {
    return (u & 0x80000000u) ? __uint_as_float(u ^ 0x80000000u) : __uint_as_float(~u);
}
__device__ __forceinline__ float ex2(float x) {
    float r;
    asm("ex2.approx.f32 %0, %1;" : "=f"(r) : "f"(x));
    return r;
}
__device__ __forceinline__ unsigned pack_hilo(float x, float y, unsigned& loOut) {
    __half hx = __float2half_rn(x), hy = __float2half_rn(y);
    __half lx = __float2half_rn(x - __half2float(hx));
    __half ly = __float2half_rn(y - __half2float(hy));
    loOut = (unsigned)__half_as_ushort(lx) | ((unsigned)__half_as_ushort(ly) << 16);
    return (unsigned)__half_as_ushort(hx) | ((unsigned)__half_as_ushort(hy) << 16);
}

// m16n8k16 fp16 mma, fp32 accumulate: D += A*B (row.col)
__device__ __forceinline__ void mma_f16(float* c, const uint4& a, const uint2& b) {
    asm volatile(
        "mma.sync.aligned.m16n8k16.row.col.f32.f16.f16.f32 "
        "{%0,%1,%2,%3}, {%4,%5,%6,%7}, {%8,%9}, {%0,%1,%2,%3};"
        : "+f"(c[0]), "+f"(c[1]), "+f"(c[2]), "+f"(c[3])
        : "r"(a.x), "r"(a.y), "r"(a.z), "r"(a.w), "r"(b.x), "r"(b.y));
}

// ---------------- kernel: one-time fp16 hi/lo conversion into fragment layouts ----------------
// blocks [0,256): A slots; [256,768): B slots; block 768: targets + out[0] init
__global__ void k_cvt(const float* __restrict__ X, const int* __restrict__ tgt,
                      float* __restrict__ out, int out_size) {
    const int b = blockIdx.x, tid = threadIdx.x;
    if (b < 256) {
        int f = b * 256 + tid;                    // 0..65535
        int t = f >> 8, rem = f & 255, s = rem >> 5, l = rem & 31;
        int g = l >> 2, q = l & 3;
        int m0 = t * 16 + g, k0 = s * 16 + 2 * q;
        const int mm[4] = {m0, m0 + 8, m0, m0 + 8};
        const int kk[4] = {k0, k0, k0 + 8, k0 + 8};
        unsigned hiU[4], loU[4];
        #pragma unroll
        for (int r = 0; r < 4; r++) {
            float2 v = *reinterpret_cast<const float2*>(&X[mm[r] * D + kk[r]]);
            hiU[r] = pack_hilo(v.x, v.y, loU[r]);
        }
        *reinterpret_cast<uint4*>(&g_Ah[(size_t)f * 4]) = make_uint4(hiU[0], hiU[1], hiU[2], hiU[3]);
        *reinterpret_cast<uint4*>(&g_Al[(size_t)f * 4]) = make_uint4(loU[0], loU[1], loU[2], loU[3]);
    } else if (b < 768) {
        int f = (b - 256) * 256 + tid;            // 0..131071
        int nt = f >> 8, rem = f & 255, s = rem >> 5, l = rem & 31;
        int g = l >> 2, q = l & 3;
        int n0 = nt * 8 + g, k0 = s * 16 + 2 * q;
        unsigned hiU[2], loU[2];
        #pragma unroll
        for (int r = 0; r < 2; r++) {
            float2 v = *reinterpret_cast<const float2*>(&X[n0 * D + k0 + 8 * r]);
            hiU[r] = pack_hilo(v.x, v.y, loU[r]);
        }
        *reinterpret_cast<uint2*>(&g_Bh[(size_t)f * 2]) = make_uint2(hiU[0], hiU[1]);
        *reinterpret_cast<uint2*>(&g_Bl[(size_t)f * 2]) = make_uint2(loU[0], loU[1]);
    } else {
        __shared__ int sIs64;
        if (tid < 32) {
            int bad = 0;
            #pragma unroll
            for (int i = 0; i < 4; i++)
                if (tgt[1 + 2 * (tid + 32 * i)] != 0) bad = 1;
            unsigned ab = __ballot_sync(0xFFFFFFFFu, bad);
            if (tid == 0) sIs64 = (ab == 0);
        }
        if (tid == 0 && out_size >= 1) out[0] = 0.0f;
        __syncthreads();
        for (int j = tid; j < N; j += 256)
            g_t8[j] = sIs64 ? (unsigned char)((const long long*)tgt)[j]
                            : (unsigned char)tgt[j];
    }
}

// ---------------- kernel: sim = X X^T (2-term fp16 split, 3 passes), upper triangle ----------------
// Triangle-packed 528 blocks, 256 threads = 8 warps (2x4), warp tile 64x32.
// Mainloop: 8 k16-steps; fragments LDG'd from pre-converted layouts; no smem, no barriers.
__global__ __launch_bounds__(256, 2) void k_gemm(float* __restrict__ out, int out_size) {
    __shared__ __align__(16) float sm[9216];   // epilogue staging only (8 x 1152)

    const int tid = threadIdx.x;

    const int lin = blockIdx.x;
    int bi = (int)(32.5f - sqrtf(32.5f * 32.5f - 2.0f * (float)lin));
    #define TRI_OFF(r) ((r) * NB - ((r) * ((r) - 1)) / 2)
    while (bi > 0 && TRI_OFF(bi) > lin) bi--;
    while (bi < NB - 1 && TRI_OFF(bi + 1) <= lin) bi++;
    const int bj = bi + (lin - TRI_OFF(bi));
    #undef TRI_OFF

    const int rowBase = bi * 128;
    const int colBase = bj * 128;

    const int w    = tid >> 5;
    const int lane = tid & 31;
    const int wr   = w >> 2;
    const int wc   = w & 3;
    const int g    = lane >> 2;
    const int q    = lane & 3;

    float c[4][4][4];
    #pragma unroll
    for (int mt = 0; mt < 4; mt++)
        #pragma unroll
        for (int nt = 0; nt < 4; nt++)
            #pragma unroll
            for (int r = 0; r < 4; r++) c[mt][nt][r] = 0.0f;

    // slot bases (A slots *4 uints, B slots *2 uints)
    const int aSlot0 = ((bi * 8 + wr * 4) * 8) * 32 + lane;   // + mt*256 + s*32
    const int bSlot0 = ((bj * 16 + wc * 4) * 8) * 32 + lane;  // + nt*256 + s*32

    #pragma unroll 2
    for (int s = 0; s < 8; s++) {
        uint4 ah[4], al[4];
        uint2 bh[4], bl[4];
        #pragma unroll
        for (int mt = 0; mt < 4; mt++) {
            size_t idx = (size_t)(aSlot0 + mt * 256 + s * 32) * 4;
            ah[mt] = *reinterpret_cast<const uint4*>(&g_Ah[idx]);
            al[mt] = *reinterpret_cast<const uint4*>(&g_Al[idx]);
        }
        #pragma unroll
        for (int nt = 0; nt < 4; nt++) {
            size_t idx = (size_t)(bSlot0 + nt * 256 + s * 32) * 2;
            bh[nt] = *reinterpret_cast<const uint2*>(&g_Bh[idx]);
            bl[nt] = *reinterpret_cast<const uint2*>(&g_Bl[idx]);
        }
        #pragma unroll
        for (int mt = 0; mt < 4; mt++)
            #pragma unroll
            for (int nt = 0; nt < 4; nt++) {
                mma_f16(c[mt][nt], ah[mt], bh[nt]);
                mma_f16(c[mt][nt], ah[mt], bl[nt]);
                mma_f16(c[mt][nt], al[mt], bh[nt]);
            }
    }

    // ---------------- epilogue (verified; C layout identical to tf32 path) ----------------
    int trow[8], tcol[8];
    #pragma unroll
    for (int mt = 0; mt < 4; mt++)
        #pragma unroll
        for (int h = 0; h < 2; h++)
            trow[mt * 2 + h] = g_t8[rowBase + wr * 64 + mt * 16 + g + 8 * h];
    #pragma unroll
    for (int nt = 0; nt < 4; nt++)
        #pragma unroll
        for (int p = 0; p < 2; p++)
            tcol[nt * 2 + p] = g_t8[colBase + wc * 32 + nt * 8 + q * 2 + p];

    float rMin[8], rMax[8], cMin[8], cMax[8];
    #pragma unroll
    for (int k = 0; k < 8; k++) { rMin[k] = BIGF; rMax[k] = -BIGF; cMin[k] = BIGF; cMax[k] = -BIGF; }
    #pragma unroll
    for (int mt = 0; mt < 4; mt++)
        #pragma unroll
        for (int nt = 0; nt < 4; nt++)
            #pragma unroll
            for (int r = 0; r < 4; r++) {
                int h = r >> 1, p = r & 1;
                float s = c[mt][nt][r];
                if (trow[mt * 2 + h] == tcol[nt * 2 + p]) {
                    if (s < 1.0f) {
                        rMin[mt * 2 + h] = fminf(rMin[mt * 2 + h], s);
                        cMin[nt * 2 + p] = fminf(cMin[nt * 2 + p], s);
                    }
                } else {
                    rMax[mt * 2 + h] = fmaxf(rMax[mt * 2 + h], s);
                    cMax[nt * 2 + p] = fmaxf(cMax[nt * 2 + p], s);
                }
            }

    #pragma unroll
    for (int o = 1; o <= 2; o <<= 1)
        #pragma unroll
        for (int k = 0; k < 8; k++) {
            rMin[k] = fminf(rMin[k], __shfl_xor_sync(0xFFFFFFFFu, rMin[k], o));
            rMax[k] = fmaxf(rMax[k], __shfl_xor_sync(0xFFFFFFFFu, rMax[k], o));
        }
    if (q == 0) {
        #pragma unroll
        for (int k = 0; k < 8; k++) {
            int row = rowBase + wr * 64 + (k >> 1) * 16 + g + 8 * (k & 1);
            atomicMax(&g_eminpos[row], f2u(-rMin[k]));
            atomicMax(&g_emaxneg[row], f2u(rMax[k]));
        }
    }
    #pragma unroll
    for (int o = 4; o <= 16; o <<= 1)
        #pragma unroll
        for (int k = 0; k < 8; k++) {
            cMin[k] = fminf(cMin[k], __shfl_xor_sync(0xFFFFFFFFu, cMin[k], o));
            cMax[k] = fmaxf(cMax[k], __shfl_xor_sync(0xFFFFFFFFu, cMax[k], o));
        }
    if (g == 0) {
        #pragma unroll
        for (int k = 0; k < 8; k++) {
            int col = colBase + wc * 32 + (k >> 1) * 8 + q * 2 + (k & 1);
            atomicMax(&g_eminpos[col], f2u(-cMin[k]));
            atomicMax(&g_emaxneg[col], f2u(cMax[k]));
        }
    }

    float* S = sm + w * 1152;
    #pragma unroll
    for (int h2 = 0; h2 < 2; h2++) {
        #pragma unroll
        for (int mt2 = 0; mt2 < 2; mt2++) {
            int mt = h2 * 2 + mt2;
            #pragma unroll
            for (int nt = 0; nt < 4; nt++)
                #pragma unroll
                for (int r = 0; r < 4; r++)
                    S[(mt2 * 16 + g + 8 * (r >> 1)) * 36 + nt * 8 + q * 2 + (r & 1)] = c[mt][nt][r];
        }
        __syncwarp();
        #pragma unroll
        for (int pass = 0; pass < 8; pass++) {
            int idx = pass * 32 + lane;
            int lr = idx >> 3, qq = idx & 7;
            float4 v = *reinterpret_cast<const float4*>(&S[lr * 36 + qq * 4]);
            *reinterpret_cast<float4*>(
                &g_sim[(size_t)(rowBase + wr * 64 + h2 * 32 + lr) * N + colBase + wc * 32 + qq * 4]) = v;
        }
        __syncwarp();
        #pragma unroll
        for (int mt2 = 0; mt2 < 2; mt2++) {
            int mt = h2 * 2 + mt2;
            #pragma unroll
            for (int nt = 0; nt < 4; nt++)
                #pragma unroll
                for (int r = 0; r < 4; r++)
                    S[(nt * 8 + q * 2 + (r & 1)) * 36 + mt2 * 16 + g + 8 * (r >> 1)] = c[mt][nt][r];
        }
        __syncwarp();
        #pragma unroll
        for (int pass = 0; pass < 8; pass++) {
            int idx = pass * 32 + lane;
            int lr = idx >> 3, qq = idx & 7;
            float4 v = *reinterpret_cast<const float4*>(&S[lr * 36 + qq * 4]);
            *reinterpret_cast<float4*>(
                &g_sim[(size_t)(colBase + wc * 32 + lr) * N + rowBase + wr * 64 + h2 * 32 + qq * 4]) = v;
        }
        __syncwarp();
    }
}

// ---------------- kernel: mining (branchless) + masked exp sums + loss ----------------
__global__ __launch_bounds__(256) void k_mine(const float* __restrict__ margin,
                                              const float* __restrict__ weight,
                                              float* __restrict__ out, int out_size) {
    const int lane = threadIdx.x & 31;
    const int warp = threadIdx.x >> 5;
    const int row  = blockIdx.x * 8 + warp;

    const float4* srow4 = reinterpret_cast<const float4*>(&g_sim[(size_t)row * N]);
    const uchar4* t4    = reinterpret_cast<const uchar4*>(g_t8);

    const int   tr = g_t8[row];
    const float m  = margin[row];
    const float wt = weight[row];
    unsigned um = g_eminpos[row];
    unsigned ux = g_emaxneg[row];
    const float minp = um ? -u2f(um) : BIGF;
    const float maxn = ux ? u2f(ux) : -BIGF;

    const float kn = ALPHA * wt * LOG2E, cn = -ALPHA * BASE * LOG2E;
    const float kp = -BETA * wt * LOG2E, cp = BETA * BASE * LOG2E;

    float ps = 0.f, ns = 0.f;
    int ap = 0, an = 0;

    #define PROC(S, TJ)                                                     \
        do {                                                                \
            float s_ = (S);                                                 \
            bool isP = ((int)(TJ) == tr);                                   \
            float en = ex2(fmaf(s_, kn, cn));                               \
            float ep = ex2(fmaf(s_, kp, cp));                               \
            bool pc = isP && (s_ < 1.0f) && ((maxn - s_) + m > 0.0f);       \
            bool nc = (!isP) && (((s_ + m) - minp) > 0.0f);                 \
            ps += pc ? ep : 0.0f;                                           \
            ns += nc ? en : 0.0f;                                           \
            ap += pc;                                                       \
            an += nc;                                                       \
        } while (0)

    #pragma unroll
    for (int cch = 0; cch < 4; cch++) {
        float4 s[8];
        uchar4 t[8];
        #pragma unroll
        for (int i = 0; i < 8; i++) {
            int idx = cch * 256 + i * 32 + lane;
            s[i] = srow4[idx];
            t[i] = t4[idx];
        }
        #pragma unroll
        for (int i = 0; i < 8; i++) {
            PROC(s[i].x, t[i].x);
            PROC(s[i].y, t[i].y);
            PROC(s[i].z, t[i].z);
            PROC(s[i].w, t[i].w);
        }
    }
    #undef PROC

    #pragma unroll
    for (int o = 16; o >= 1; o >>= 1) {
        ps += __shfl_xor_sync(0xFFFFFFFFu, ps, o);
        ns += __shfl_xor_sync(0xFFFFFFFFu, ns, o);
        ap += __shfl_xor_sync(0xFFFFFFFFu, ap, o);
        an += __shfl_xor_sync(0xFFFFFFFFu, an, o);
    }

    if (lane == 0) {
        int valid = (ap + an) >= 1;
        float li = valid ? ((2.0f / BETA) * log1pf(ps) + (2.0f / ALPHA) * log1pf(ns)) : 0.0f;
        if (out_size >= 1) atomicAdd(out, li * (1.0f / (float)N));
        if (out_size >= 1 + 2 * N) {
            out[1 + row]     = valid ? (float)ap : 0.0f;
            out[1 + N + row] = valid ? (float)an : 0.0f;
        }
    }
}

// ---------------- launch ----------------
extern "C" void kernel_launch(void* const* d_in, const int* in_sizes, int n_in,
                              void* d_out, int out_size) {
    const float* X      = (const float*)d_in[0];
    const int*   tgt    = (const int*)d_in[1];
    const float* margin = (const float*)d_in[2];
    const float* weight = (const float*)d_in[3];
    float* out = (float*)d_out;

    k_cvt<<<769, 256>>>(X, tgt, out, out_size);
    k_gemm<<<528, 256>>>(out, out_size);
    k_mine<<<512, 256>>>(margin, weight, out, out_size);
}